// round 8
// baseline (speedup 1.0000x reference)
#include <cuda_runtime.h>
#include <cuda_bf16.h>
#include <math.h>
#include <stdint.h>

// ---------------------------------------------------------------------------
// Problem constants
// ---------------------------------------------------------------------------
#define BATCH   8192
#define IN_DIM  4096
#define OUT_DIM 2048
#define DEPTH   9
#define RSTEPS  27
#define WIN     55
#define CENTER  27

// GEMM tiling: 128x64 CTA tile, 2 CTAs/SM, BK=16, 8 stages, 4-chunk epochs
#define BM 128
#define BN 64
#define BK 16
#define NKT (IN_DIM / BK)            // 256
#define STAGES 8
// Stage layout: Ahi 4K | Alo 4K | Bhi 2K | Blo 2K
#define AHI 0
#define ALO 4096
#define BHI 8192
#define BLO 10240
#define STAGE_BYTES 12288
#define SMEM_TOTAL (STAGES * STAGE_BYTES)   // 98304/CTA -> 2 CTAs = 192KB/SM

// ---------------------------------------------------------------------------
// Device-global scratch (static: no runtime allocation)
// ---------------------------------------------------------------------------
__device__ float         g_pb[OUT_DIM];
__device__ __nv_bfloat16 g_xhi[(size_t)BATCH * IN_DIM];
__device__ __nv_bfloat16 g_xlo[(size_t)BATCH * IN_DIM];
__device__ __nv_bfloat16 g_wThi[(size_t)OUT_DIM * IN_DIM];   // W^T [N][K]
__device__ __nv_bfloat16 g_wTlo[(size_t)OUT_DIM * IN_DIM];

// ---------------------------------------------------------------------------
// PTX helpers (base sm_103 ISA only: cp.async / ldmatrix / mma.sync)
// ---------------------------------------------------------------------------
__device__ __forceinline__ uint32_t smem_u32(const void* p) {
    uint32_t a;
    asm("{ .reg .u64 t; cvta.to.shared.u64 t, %1; cvt.u32.u64 %0, t; }"
        : "=r"(a) : "l"(p));
    return a;
}
__device__ __forceinline__ void cpasync16(uint32_t dst, const void* src) {
    asm volatile("cp.async.cg.shared.global [%0], [%1], 16;"
                 :: "r"(dst), "l"(src));
}
#define CP_COMMIT() asm volatile("cp.async.commit_group;" ::: "memory")
#define CP_WAIT0()  asm volatile("cp.async.wait_group 0;"  ::: "memory")

#define LDSM_X4(d, a) \
    asm volatile("ldmatrix.sync.aligned.m8n8.x4.shared.b16 {%0,%1,%2,%3}, [%4];" \
        : "=r"((d)[0]), "=r"((d)[1]), "=r"((d)[2]), "=r"((d)[3]) : "r"(a))
#define LDSM_X2(d, a) \
    asm volatile("ldmatrix.sync.aligned.m8n8.x2.shared.b16 {%0,%1}, [%2];" \
        : "=r"((d)[0]), "=r"((d)[1]) : "r"(a))

#define MMA16816(c, a, b) \
    asm volatile("mma.sync.aligned.m16n8k16.row.col.f32.bf16.bf16.f32 " \
        "{%0,%1,%2,%3}, {%4,%5,%6,%7}, {%8,%9}, {%0,%1,%2,%3};" \
        : "+f"((c)[0]), "+f"((c)[1]), "+f"((c)[2]), "+f"((c)[3]) \
        : "r"((a)[0]), "r"((a)[1]), "r"((a)[2]), "r"((a)[3]), \
          "r"((b)[0]), "r"((b)[1]))

// Swizzled smem offset for logical (row, 16B-chunk c in 0..1) of a 32B-row
// tile. Physical: 128B rows packing 4 logical rows; chunk8 = ((row&3)<<1)|c,
// XOR (p&7). Verified: any ldmatrix 8-lane group hits 8 distinct 16B chunks.
__device__ __forceinline__ uint32_t swz(uint32_t base, int row, int c) {
    int p  = row >> 2;
    int c8 = ((row & 3) << 1) | c;
    return base + p * 128 + ((c8 ^ (p & 7)) << 4);
}

// ---------------------------------------------------------------------------
// Kernel 1: universal probs (dependency-cone trick) + bias -> g_pb
// ---------------------------------------------------------------------------
__global__ void probs_kernel(const float* __restrict__ uw,
                             const float* __restrict__ bias) {
    int o = blockIdx.x * blockDim.x + threadIdx.x;
    if (o >= OUT_DIM) return;
    float w[WIN];
#pragma unroll
    for (int j = 0; j < WIN; j++) w[j] = 0.015625f;   // 1/sqrt(4096)
#pragma unroll
    for (int t = 0; t < RSTEPS; t++) {
        const int d = t / 3, g = t % 3;
        float ang = uw[(size_t)d * IN_DIM * OUT_DIM + (size_t)o * OUT_DIM + g];
        float s, c;
        sincosf(ang, &s, &c);
        float nw[WIN];
        nw[0] = w[0]; nw[WIN - 1] = w[WIN - 1];
#pragma unroll
        for (int j = 1; j < WIN - 1; j++)
            nw[j] = c * w[j] - s * w[j + 1] + s * w[j - 1];
#pragma unroll
        for (int j = 0; j < WIN; j++) w[j] = nw[j];
    }
    g_pb[o] = w[CENTER] * w[CENTER] + bias[o];
}

// ---------------------------------------------------------------------------
// Kernel 2: split x -> (hi, lo) bf16
// ---------------------------------------------------------------------------
__global__ void split_x_kernel(const float* __restrict__ x) {
    size_t i = ((size_t)blockIdx.x * blockDim.x + threadIdx.x) * 4;
    float4 v = *(const float4*)(x + i);
    __nv_bfloat16 h0 = __float2bfloat16(v.x);
    __nv_bfloat16 h1 = __float2bfloat16(v.y);
    __nv_bfloat16 h2 = __float2bfloat16(v.z);
    __nv_bfloat16 h3 = __float2bfloat16(v.w);
    __nv_bfloat162* ph = (__nv_bfloat162*)(g_xhi + i);
    __nv_bfloat162* pl = (__nv_bfloat162*)(g_xlo + i);
    ph[0] = __nv_bfloat162(h0, h1);
    ph[1] = __nv_bfloat162(h2, h3);
    pl[0] = __nv_bfloat162(__float2bfloat16(v.x - __bfloat162float(h0)),
                           __float2bfloat16(v.y - __bfloat162float(h1)));
    pl[1] = __nv_bfloat162(__float2bfloat16(v.z - __bfloat162float(h2)),
                           __float2bfloat16(v.w - __bfloat162float(h3)));
}

// ---------------------------------------------------------------------------
// Kernel 3: transpose + split W[k][n] -> wT_hi/lo[n][k]
// ---------------------------------------------------------------------------
__global__ void split_w_kernel(const float* __restrict__ W) {
    __shared__ float t[32][33];
    const int n0 = blockIdx.x * 32, k0 = blockIdx.y * 32;
    const int tx = threadIdx.x, ty = threadIdx.y;   // 32 x 8
#pragma unroll
    for (int i = 0; i < 32; i += 8)
        t[ty + i][tx] = W[(size_t)(k0 + ty + i) * OUT_DIM + n0 + tx];
    __syncthreads();
#pragma unroll
    for (int i = 0; i < 32; i += 8) {
        float v = t[tx][ty + i];
        __nv_bfloat16 h = __float2bfloat16(v);
        size_t o = (size_t)(n0 + ty + i) * IN_DIM + k0 + tx;
        g_wThi[o] = h;
        g_wTlo[o] = __float2bfloat16(v - __bfloat162float(h));
    }
}

// ---------------------------------------------------------------------------
// Kernel 4: C = tanh(x @ W + g_pb) via bf16x3 mma.sync GEMM.
// 128x64x16 chunks, 8-deep smem ring, 4-chunk epochs: ONE __syncthreads per
// 4 chunks (refilled slots were consumed last epoch; top barrier protects).
// Fragment double-buffering chains across chunks inside the epoch.
// ---------------------------------------------------------------------------
__global__ __launch_bounds__(256, 2)
void gemm_bf16x3_kernel(float* __restrict__ out) {
    extern __shared__ char smem[];
    const uint32_t sb = smem_u32(smem);

    const int tid  = threadIdx.x;
    const int lane = tid & 31;
    const int wid  = tid >> 5;
    const int wm   = wid >> 1;          // 0..3  -> m offset wm*32
    const int wn   = wid & 1;           // 0..1  -> n offset wn*32
    const int gid  = lane >> 2;
    const int tg   = lane & 3;
    const int bm   = blockIdx.y * BM;
    const int bn   = blockIdx.x * BN;

    // --- global load mapping: 3 x 16B chunks per thread per chunk ---
    // A (hi+lo): 128 rows x 2 chunks -> row = tid>>1, c = tid&1 (one each)
    // B: tid<128 -> Bhi, tid>=128 -> Blo; row = (tid&127)>>1, c = tid&1
    const int rA = tid >> 1;
    const int cA = tid & 1;
    const int rB = (tid & 127) >> 1;
    const int cB = tid & 1;

    const __nv_bfloat16* pAh = g_xhi + (size_t)(bm + rA) * IN_DIM + cA * 8;
    const __nv_bfloat16* pAl = g_xlo + (size_t)(bm + rA) * IN_DIM + cA * 8;
    const __nv_bfloat16* pB  = ((tid < 128) ? g_wThi : g_wTlo)
                               + (size_t)(bn + rB) * IN_DIM + cB * 8;

    const uint32_t dAh = swz(AHI, rA, cA);
    const uint32_t dAl = swz(ALO, rA, cA);
    const uint32_t dB  = swz((tid < 128) ? BHI : BLO, rB, cB);

#define ISSUE_CHUNK(c)                                                       \
    do {                                                                     \
        uint32_t s_ = sb + ((c) & 7) * STAGE_BYTES;                          \
        int ko_ = (c) * BK;                                                  \
        cpasync16(s_ + dAh, pAh + ko_);                                      \
        cpasync16(s_ + dAl, pAl + ko_);                                      \
        cpasync16(s_ + dB,  pB  + ko_);                                      \
    } while (0)

    float acc[2][4][4];
#pragma unroll
    for (int i = 0; i < 2; i++)
#pragma unroll
        for (int j = 0; j < 4; j++)
#pragma unroll
            for (int q = 0; q < 4; q++) acc[i][j][q] = 0.0f;

    // Per-lane ldmatrix logical coordinates (chunk-invariant with BK=16)
    const int a_rl = lane & 15;           // A: rows m0..m0+15
    const int a_ch = lane >> 4;           // A: chunk 0/1 of the 32B row
    const int b_rl = lane & 7;            // B: rows n0..n0+7
    const int b_ch = (lane >> 3) & 1;     // B: chunk 0/1

    uint32_t oA[2], oB[4];
#pragma unroll
    for (int mi = 0; mi < 2; mi++)
        oA[mi] = swz(0, wm * 32 + mi * 16 + a_rl, a_ch);
#pragma unroll
    for (int ni = 0; ni < 4; ni++)
        oB[ni] = swz(0, wn * 32 + ni * 8 + b_rl, b_ch);

    // Fragment registers: hi double-buffered, lo just-in-time
    uint32_t ah0[2][4], ah1[2][4];
    uint32_t bh0[4][2], bh1[4][2];
    uint32_t al[2][4],  bl[4][2];

#define LOAD_HI(AH, BH, SBASE)                                               \
    do {                                                                     \
        LDSM_X4(AH[0], (SBASE) + AHI + oA[0]);                               \
        LDSM_X4(AH[1], (SBASE) + AHI + oA[1]);                               \
        LDSM_X2(BH[0], (SBASE) + BHI + oB[0]);                               \
        LDSM_X2(BH[1], (SBASE) + BHI + oB[1]);                               \
        LDSM_X2(BH[2], (SBASE) + BHI + oB[2]);                               \
        LDSM_X2(BH[3], (SBASE) + BHI + oB[3]);                               \
    } while (0)

#define LOAD_LO(SBASE)                                                       \
    do {                                                                     \
        LDSM_X4(al[0], (SBASE) + ALO + oA[0]);                               \
        LDSM_X4(al[1], (SBASE) + ALO + oA[1]);                               \
        LDSM_X2(bl[0], (SBASE) + BLO + oB[0]);                               \
        LDSM_X2(bl[1], (SBASE) + BLO + oB[1]);                               \
        LDSM_X2(bl[2], (SBASE) + BLO + oB[2]);                               \
        LDSM_X2(bl[3], (SBASE) + BLO + oB[3]);                               \
    } while (0)

    // hh first (hi preloaded long ago), then hl / lh (lo just loaded, its
    // LDSM latency covered by the 8 hh MMAs).
#define MMA_PHASE(AH, BH)                                                    \
    do {                                                                     \
        _Pragma("unroll")                                                    \
        for (int mi = 0; mi < 2; mi++)                                       \
            _Pragma("unroll")                                                \
            for (int ni = 0; ni < 4; ni++)                                   \
                MMA16816(acc[mi][ni], AH[mi], BH[ni]);                       \
        _Pragma("unroll")                                                    \
        for (int mi = 0; mi < 2; mi++)                                       \
            _Pragma("unroll")                                                \
            for (int ni = 0; ni < 4; ni++)                                   \
                MMA16816(acc[mi][ni], AH[mi], bl[ni]);                       \
        _Pragma("unroll")                                                    \
        for (int mi = 0; mi < 2; mi++)                                       \
            _Pragma("unroll")                                                \
            for (int ni = 0; ni < 4; ni++)                                   \
                MMA16816(acc[mi][ni], al[mi], BH[ni]);                       \
    } while (0)

    // Prologue: epoch-0 data (chunks 0..3)
    ISSUE_CHUNK(0); ISSUE_CHUNK(1); ISSUE_CHUNK(2); ISSUE_CHUNK(3);
    CP_COMMIT();
    CP_WAIT0();
    __syncthreads();
    LOAD_HI(ah0, bh0, sb);              // chunk 0, slot 0

#pragma unroll 1
    for (int e = 0; e < NKT / 4; e++) {
        const int c0 = e * 4;
        // Refill next epoch's 4 chunks into slots freed last epoch
        // (top barrier of this epoch already passed -> safe).
        if (e + 1 < NKT / 4) {
            ISSUE_CHUNK(c0 + 4); ISSUE_CHUNK(c0 + 5);
            ISSUE_CHUNK(c0 + 6); ISSUE_CHUNK(c0 + 7);
            CP_COMMIT();
        }

        const uint32_t s0 = sb + ((c0    ) & 7) * STAGE_BYTES;
        const uint32_t s1 = sb + ((c0 + 1) & 7) * STAGE_BYTES;
        const uint32_t s2 = sb + ((c0 + 2) & 7) * STAGE_BYTES;
        const uint32_t s3 = sb + ((c0 + 3) & 7) * STAGE_BYTES;

        LOAD_LO(s0); LOAD_HI(ah1, bh1, s1); MMA_PHASE(ah0, bh0);
        LOAD_LO(s1); LOAD_HI(ah0, bh0, s2); MMA_PHASE(ah1, bh1);
        LOAD_LO(s2); LOAD_HI(ah1, bh1, s3); MMA_PHASE(ah0, bh0);
        LOAD_LO(s3);                        MMA_PHASE(ah1, bh1);

        // Epoch boundary: next epoch's chunks were issued a full epoch ago.
        if (e + 1 < NKT / 4) {
            CP_WAIT0();
            __syncthreads();
            LOAD_HI(ah0, bh0, sb + ((c0 + 4) & 7) * STAGE_BYTES);
        }
    }

    // ------------------- epilogue: +pb, tanh, store -------------------
    float pbv[4][2];
#pragma unroll
    for (int ni = 0; ni < 4; ni++) {
        const int col = bn + wn * 32 + ni * 8 + tg * 2;
        pbv[ni][0] = g_pb[col];
        pbv[ni][1] = g_pb[col + 1];
    }
#pragma unroll
    for (int mi = 0; mi < 2; mi++) {
        const int r0 = bm + wm * 32 + mi * 16 + gid;
#pragma unroll
        for (int ni = 0; ni < 4; ni++) {
            const int col = bn + wn * 32 + ni * 8 + tg * 2;
            float2 v0, v1;
            v0.x = tanhf(acc[mi][ni][0] + pbv[ni][0]);
            v0.y = tanhf(acc[mi][ni][1] + pbv[ni][1]);
            v1.x = tanhf(acc[mi][ni][2] + pbv[ni][0]);
            v1.y = tanhf(acc[mi][ni][3] + pbv[ni][1]);
            *(float2*)(out + (size_t)r0 * OUT_DIM + col)       = v0;
            *(float2*)(out + (size_t)(r0 + 8) * OUT_DIM + col) = v1;
        }
    }
}

// ---------------------------------------------------------------------------
// Host launch
// ---------------------------------------------------------------------------
extern "C" void kernel_launch(void* const* d_in, const int* in_sizes, int n_in,
                              void* d_out, int out_size) {
    const float *x = nullptr, *uw = nullptr, *cw = nullptr, *cb = nullptr;
    for (int i = 0; i < n_in; i++) {
        switch (in_sizes[i]) {
            case BATCH * IN_DIM:           x  = (const float*)d_in[i]; break;
            case DEPTH * IN_DIM * OUT_DIM: uw = (const float*)d_in[i]; break;
            case IN_DIM * OUT_DIM:         cw = (const float*)d_in[i]; break;
            case OUT_DIM:                  cb = (const float*)d_in[i]; break;
            default: break;
        }
    }
    float* out = (float*)d_out;

    probs_kernel<<<OUT_DIM / 256, 256>>>(uw, cb);
    split_x_kernel<<<(BATCH * IN_DIM) / (4 * 256), 256>>>(x);
    split_w_kernel<<<dim3(OUT_DIM / 32, IN_DIM / 32), dim3(32, 8)>>>(cw);

    static int attr_done = 0;
    if (!attr_done) {
        cudaFuncSetAttribute(gemm_bf16x3_kernel,
                             cudaFuncAttributeMaxDynamicSharedMemorySize,
                             SMEM_TOTAL);
        attr_done = 1;
    }
    dim3 grid(OUT_DIM / BN, BATCH / BM);   // (32, 64)
    gemm_bf16x3_kernel<<<grid, 256, SMEM_TOTAL>>>(out);
}

// round 9
// speedup vs baseline: 2.2906x; 2.2906x over previous
#include <cuda_runtime.h>
#include <cuda_bf16.h>
#include <math.h>
#include <stdint.h>

// ---------------------------------------------------------------------------
// Problem constants
// ---------------------------------------------------------------------------
#define BATCH   8192
#define IN_DIM  4096
#define OUT_DIM 2048
#define DEPTH   9
#define RSTEPS  27
#define WIN     55
#define CENTER  27

// GEMM tiling: 128x64 CTA tile, 2 CTAs/SM
#define BM 128
#define BN 64
#define BK 32
#define NKT (IN_DIM / BK)            // 128
#define STAGES 4
// Stage layout: Ahi 8K | Alo 8K | Bhi 4K | Blo 4K
#define AHI 0
#define ALO 8192
#define BHI 16384
#define BLO 20480
#define STAGE_BYTES 24576
#define SMEM_TOTAL (STAGES * STAGE_BYTES)   // 98304/CTA -> 2 CTAs = 192KB/SM

// ---------------------------------------------------------------------------
// Device-global scratch (static: no runtime allocation)
// ---------------------------------------------------------------------------
__device__ float         g_pb[OUT_DIM];
__device__ __nv_bfloat16 g_xhi[(size_t)BATCH * IN_DIM];
__device__ __nv_bfloat16 g_xlo[(size_t)BATCH * IN_DIM];
__device__ __nv_bfloat16 g_wThi[(size_t)OUT_DIM * IN_DIM];   // W^T [N][K]
__device__ __nv_bfloat16 g_wTlo[(size_t)OUT_DIM * IN_DIM];

// ---------------------------------------------------------------------------
// PTX helpers (base sm_103 ISA only: cp.async / ldmatrix / mma.sync)
// ---------------------------------------------------------------------------
__device__ __forceinline__ uint32_t smem_u32(const void* p) {
    uint32_t a;
    asm("{ .reg .u64 t; cvta.to.shared.u64 t, %1; cvt.u32.u64 %0, t; }"
        : "=r"(a) : "l"(p));
    return a;
}
__device__ __forceinline__ void cpasync16(uint32_t dst, const void* src) {
    asm volatile("cp.async.cg.shared.global [%0], [%1], 16;"
                 :: "r"(dst), "l"(src));
}
#define CP_COMMIT() asm volatile("cp.async.commit_group;" ::: "memory")
#define CP_WAIT1()  asm volatile("cp.async.wait_group 1;"  ::: "memory")
#define CP_WAIT2()  asm volatile("cp.async.wait_group 2;"  ::: "memory")

#define LDSM_X4(d, a) \
    asm volatile("ldmatrix.sync.aligned.m8n8.x4.shared.b16 {%0,%1,%2,%3}, [%4];" \
        : "=r"((d)[0]), "=r"((d)[1]), "=r"((d)[2]), "=r"((d)[3]) : "r"(a))

#define MMA16816(c, a, b) \
    asm volatile("mma.sync.aligned.m16n8k16.row.col.f32.bf16.bf16.f32 " \
        "{%0,%1,%2,%3}, {%4,%5,%6,%7}, {%8,%9}, {%0,%1,%2,%3};" \
        : "+f"((c)[0]), "+f"((c)[1]), "+f"((c)[2]), "+f"((c)[3]) \
        : "r"((a)[0]), "r"((a)[1]), "r"((a)[2]), "r"((a)[3]), \
          "r"((b)[0]), "r"((b)[1]))

// Swizzled smem offset for logical (row, 16B-chunk cc 0..3) of a 64B-row tile.
__device__ __forceinline__ uint32_t swz(uint32_t base, int row, int cc) {
    int p  = row >> 1;
    int c8 = ((row & 1) << 2) | cc;
    return base + p * 128 + ((c8 ^ (p & 7)) << 4);
}

// ---------------------------------------------------------------------------
// Kernel 1: universal probs (dependency-cone trick) + bias -> g_pb
// ---------------------------------------------------------------------------
__global__ void probs_kernel(const float* __restrict__ uw,
                             const float* __restrict__ bias) {
    int o = blockIdx.x * blockDim.x + threadIdx.x;
    if (o >= OUT_DIM) return;
    float w[WIN];
#pragma unroll
    for (int j = 0; j < WIN; j++) w[j] = 0.015625f;   // 1/sqrt(4096)
#pragma unroll
    for (int t = 0; t < RSTEPS; t++) {
        const int d = t / 3, g = t % 3;
        float ang = uw[(size_t)d * IN_DIM * OUT_DIM + (size_t)o * OUT_DIM + g];
        float s, c;
        sincosf(ang, &s, &c);
        float nw[WIN];
        nw[0] = w[0]; nw[WIN - 1] = w[WIN - 1];
#pragma unroll
        for (int j = 1; j < WIN - 1; j++)
            nw[j] = c * w[j] - s * w[j + 1] + s * w[j - 1];
#pragma unroll
        for (int j = 0; j < WIN; j++) w[j] = nw[j];
    }
    g_pb[o] = w[CENTER] * w[CENTER] + bias[o];
}

// ---------------------------------------------------------------------------
// Kernel 2: split x -> (hi, lo) bf16
// ---------------------------------------------------------------------------
__global__ void split_x_kernel(const float* __restrict__ x) {
    size_t i = ((size_t)blockIdx.x * blockDim.x + threadIdx.x) * 4;
    float4 v = *(const float4*)(x + i);
    __nv_bfloat16 h0 = __float2bfloat16(v.x);
    __nv_bfloat16 h1 = __float2bfloat16(v.y);
    __nv_bfloat16 h2 = __float2bfloat16(v.z);
    __nv_bfloat16 h3 = __float2bfloat16(v.w);
    __nv_bfloat162* ph = (__nv_bfloat162*)(g_xhi + i);
    __nv_bfloat162* pl = (__nv_bfloat162*)(g_xlo + i);
    ph[0] = __nv_bfloat162(h0, h1);
    ph[1] = __nv_bfloat162(h2, h3);
    pl[0] = __nv_bfloat162(__float2bfloat16(v.x - __bfloat162float(h0)),
                           __float2bfloat16(v.y - __bfloat162float(h1)));
    pl[1] = __nv_bfloat162(__float2bfloat16(v.z - __bfloat162float(h2)),
                           __float2bfloat16(v.w - __bfloat162float(h3)));
}

// ---------------------------------------------------------------------------
// Kernel 3: transpose + split W[k][n] -> wT_hi/lo[n][k]
// ---------------------------------------------------------------------------
__global__ void split_w_kernel(const float* __restrict__ W) {
    __shared__ float t[32][33];
    const int n0 = blockIdx.x * 32, k0 = blockIdx.y * 32;
    const int tx = threadIdx.x, ty = threadIdx.y;   // 32 x 8
#pragma unroll
    for (int i = 0; i < 32; i += 8)
        t[ty + i][tx] = W[(size_t)(k0 + ty + i) * OUT_DIM + n0 + tx];
    __syncthreads();
#pragma unroll
    for (int i = 0; i < 32; i += 8) {
        float v = t[tx][ty + i];
        __nv_bfloat16 h = __float2bfloat16(v);
        size_t o = (size_t)(n0 + ty + i) * IN_DIM + k0 + tx;
        g_wThi[o] = h;
        g_wTlo[o] = __float2bfloat16(v - __bfloat162float(h));
    }
}

// ---------------------------------------------------------------------------
// Kernel 4: C = tanh(x @ W + g_pb) via bf16x3 mma.sync GEMM.
// R7 structure (best known): 128x64x32 tile, 8 warps, 4-stage ring with
// wait_group 1 + one commit per chunk, fragment double-buffering.
// R9 deltas: (1) B fragments via ldmatrix.x4 ni-pairs (MIO instr 24->16 per
// chunk); (2) cp.async refill issued mid-iteration, off the barrier exit.
// ---------------------------------------------------------------------------
__global__ __launch_bounds__(256, 2)
void gemm_bf16x3_kernel(float* __restrict__ out) {
    extern __shared__ char smem[];
    const uint32_t sb = smem_u32(smem);

    const int tid  = threadIdx.x;
    const int lane = tid & 31;
    const int wid  = tid >> 5;
    const int wm   = wid >> 1;          // 0..3  -> m offset wm*32
    const int wn   = wid & 1;           // 0..1  -> n offset wn*32
    const int gid  = lane >> 2;
    const int tg   = lane & 3;
    const int bm   = blockIdx.y * BM;
    const int bn   = blockIdx.x * BN;

    // --- global load mapping: 6 x 16B chunks per thread per stage ---
    const int rr = tid >> 2;            // rows 0..63
    const int cc = tid & 3;             // 16B chunk in 64B row

    const __nv_bfloat16* pAh0 = g_xhi  + (size_t)(bm + rr)      * IN_DIM + cc * 8;
    const __nv_bfloat16* pAh1 = g_xhi  + (size_t)(bm + rr + 64) * IN_DIM + cc * 8;
    const __nv_bfloat16* pAl0 = g_xlo  + (size_t)(bm + rr)      * IN_DIM + cc * 8;
    const __nv_bfloat16* pAl1 = g_xlo  + (size_t)(bm + rr + 64) * IN_DIM + cc * 8;
    const __nv_bfloat16* pBh  = g_wThi + (size_t)(bn + rr)      * IN_DIM + cc * 8;
    const __nv_bfloat16* pBl  = g_wTlo + (size_t)(bn + rr)      * IN_DIM + cc * 8;

    const uint32_t dAh0 = swz(AHI, rr,      cc);
    const uint32_t dAh1 = swz(AHI, rr + 64, cc);
    const uint32_t dAl0 = swz(ALO, rr,      cc);
    const uint32_t dAl1 = swz(ALO, rr + 64, cc);
    const uint32_t dBh  = swz(BHI, rr,      cc);
    const uint32_t dBl  = swz(BLO, rr,      cc);

    int kload = 0;
#define ISSUE_STAGE(stg)                                                     \
    do {                                                                     \
        uint32_t s_ = sb + (stg) * STAGE_BYTES;                              \
        cpasync16(s_ + dAh0, pAh0 + kload);                                  \
        cpasync16(s_ + dAh1, pAh1 + kload);                                  \
        cpasync16(s_ + dAl0, pAl0 + kload);                                  \
        cpasync16(s_ + dAl1, pAl1 + kload);                                  \
        cpasync16(s_ + dBh,  pBh  + kload);                                  \
        cpasync16(s_ + dBl,  pBl  + kload);                                  \
        kload += BK;                                                         \
    } while (0)

    // Prologue: fill stages 0..2 (stage 3 filled by iteration kt=0)
    ISSUE_STAGE(0); CP_COMMIT();
    ISSUE_STAGE(1); CP_COMMIT();
    ISSUE_STAGE(2); CP_COMMIT();

    float acc[2][4][4];
#pragma unroll
    for (int i = 0; i < 2; i++)
#pragma unroll
        for (int j = 0; j < 4; j++)
#pragma unroll
            for (int q = 0; q < 4; q++) acc[i][j][q] = 0.0f;

    // Per-lane ldmatrix logical coordinates
    const int a_rl = lane & 15;               // A: rows m0..m0+15
    const int a_ch = lane >> 4;               // A: +0 / +1 chunk
    // B x4 ni-pair mapping: groups of 8 lanes -> (ni,k0),(ni,k1),(ni+1,k0),(ni+1,k1)
    const int b4_row = ((lane >> 4) << 3) + (lane & 7);
    const int b4_c   = (lane >> 3) & 1;

    // Precomputed swizzled offsets (relative to stage base), both ks halves
    uint32_t oA[2][2], oB[2][2];              // oB: [ks][nj] nj = ni-pair
#pragma unroll
    for (int ks = 0; ks < 2; ks++) {
        const int ccA = ks * 2 + a_ch;
        const int ccB = ks * 2 + b4_c;
#pragma unroll
        for (int mi = 0; mi < 2; mi++)
            oA[ks][mi] = swz(0, wm * 32 + mi * 16 + a_rl, ccA);
#pragma unroll
        for (int nj = 0; nj < 2; nj++)
            oB[ks][nj] = swz(0, wn * 32 + nj * 16 + b4_row, ccB);
    }

    // Fragment registers: hi double-buffered (phase 0 / phase 1), lo single
    uint32_t ah0[2][4], ah1[2][4];            // A-hi, phase buffers
    uint32_t bh0[4][2], bh1[4][2];            // B-hi, phase buffers
    uint32_t al[2][4],  bl[4][2];             // lo, just-in-time

    // B x4: one instr fills frags ni=2*nj and 2*nj+1 (arrays contiguous)
#define LOAD_HI(AH, BH, SBASE, KS)                                           \
    do {                                                                     \
        LDSM_X4(AH[0],    (SBASE) + AHI + oA[KS][0]);                        \
        LDSM_X4(AH[1],    (SBASE) + AHI + oA[KS][1]);                        \
        LDSM_X4(&BH[0][0], (SBASE) + BHI + oB[KS][0]);                       \
        LDSM_X4(&BH[2][0], (SBASE) + BHI + oB[KS][1]);                       \
    } while (0)

#define LOAD_LO(SBASE, KS)                                                   \
    do {                                                                     \
        LDSM_X4(al[0],    (SBASE) + ALO + oA[KS][0]);                        \
        LDSM_X4(al[1],    (SBASE) + ALO + oA[KS][1]);                        \
        LDSM_X4(&bl[0][0], (SBASE) + BLO + oB[KS][0]);                       \
        LDSM_X4(&bl[2][0], (SBASE) + BLO + oB[KS][1]);                       \
    } while (0)

    // hh first (hi preloaded a phase ago), then hl / lh (lo just loaded,
    // its LDSM latency covered by the 8 hh MMAs).
#define MMA_PHASE(AH, BH)                                                    \
    do {                                                                     \
        _Pragma("unroll")                                                    \
        for (int mi = 0; mi < 2; mi++)                                       \
            _Pragma("unroll")                                                \
            for (int ni = 0; ni < 4; ni++)                                   \
                MMA16816(acc[mi][ni], AH[mi], BH[ni]);                       \
        _Pragma("unroll")                                                    \
        for (int mi = 0; mi < 2; mi++)                                       \
            _Pragma("unroll")                                                \
            for (int ni = 0; ni < 4; ni++)                                   \
                MMA16816(acc[mi][ni], AH[mi], bl[ni]);                       \
        _Pragma("unroll")                                                    \
        for (int mi = 0; mi < 2; mi++)                                       \
            _Pragma("unroll")                                                \
            for (int ni = 0; ni < 4; ni++)                                   \
                MMA16816(acc[mi][ni], al[mi], BH[ni]);                       \
    } while (0)

    // Prologue fragment load: phase-0 hi of chunk 0
    CP_WAIT2();
    __syncthreads();
    LOAD_HI(ah0, bh0, sb + 0 * STAGE_BYTES, 0);

#pragma unroll 1
    for (int kt = 0; kt < NKT; kt++) {
        // wait_group 1: groups up to kt+1 complete -> stage kt+1 readable
        CP_WAIT1();
        __syncthreads();

        const uint32_t s_cur = sb + (kt & 3) * STAGE_BYTES;
        const uint32_t s_nxt = sb + ((kt + 1) & 3) * STAGE_BYTES;

        // ---- phase ks=0: consume (ah0,bh0), prefetch ks=1 hi ----
        LOAD_LO(s_cur, 0);
        LOAD_HI(ah1, bh1, s_cur, 1);
        MMA_PHASE(ah0, bh0);

        // Refill slot (kt+3)&3 (consumed at iter kt-1; barrier passed).
        // Issued mid-iteration: LSU burst overlaps tensor work instead of
        // competing with LDSM right at barrier exit.
        if (kt + 3 < NKT) {
            ISSUE_STAGE((kt + 3) & 3);
        }
        CP_COMMIT();

        // ---- phase ks=1: consume (ah1,bh1), prefetch next chunk ks=0 hi ----
        LOAD_LO(s_cur, 1);
        LOAD_HI(ah0, bh0, s_nxt, 0);    // stale read at kt=NKT-1: never consumed
        MMA_PHASE(ah1, bh1);
    }

    // ------------------- epilogue: +pb, tanh, store -------------------
    float pbv[4][2];
#pragma unroll
    for (int ni = 0; ni < 4; ni++) {
        const int col = bn + wn * 32 + ni * 8 + tg * 2;
        pbv[ni][0] = g_pb[col];
        pbv[ni][1] = g_pb[col + 1];
    }
#pragma unroll
    for (int mi = 0; mi < 2; mi++) {
        const int r0 = bm + wm * 32 + mi * 16 + gid;
#pragma unroll
        for (int ni = 0; ni < 4; ni++) {
            const int col = bn + wn * 32 + ni * 8 + tg * 2;
            float2 v0, v1;
            v0.x = tanhf(acc[mi][ni][0] + pbv[ni][0]);
            v0.y = tanhf(acc[mi][ni][1] + pbv[ni][1]);
            v1.x = tanhf(acc[mi][ni][2] + pbv[ni][0]);
            v1.y = tanhf(acc[mi][ni][3] + pbv[ni][1]);
            *(float2*)(out + (size_t)r0 * OUT_DIM + col)       = v0;
            *(float2*)(out + (size_t)(r0 + 8) * OUT_DIM + col) = v1;
        }
    }
}

// ---------------------------------------------------------------------------
// Host launch
// ---------------------------------------------------------------------------
extern "C" void kernel_launch(void* const* d_in, const int* in_sizes, int n_in,
                              void* d_out, int out_size) {
    const float *x = nullptr, *uw = nullptr, *cw = nullptr, *cb = nullptr;
    for (int i = 0; i < n_in; i++) {
        switch (in_sizes[i]) {
            case BATCH * IN_DIM:           x  = (const float*)d_in[i]; break;
            case DEPTH * IN_DIM * OUT_DIM: uw = (const float*)d_in[i]; break;
            case IN_DIM * OUT_DIM:         cw = (const float*)d_in[i]; break;
            case OUT_DIM:                  cb = (const float*)d_in[i]; break;
            default: break;
        }
    }
    float* out = (float*)d_out;

    probs_kernel<<<OUT_DIM / 256, 256>>>(uw, cb);
    split_x_kernel<<<(BATCH * IN_DIM) / (4 * 256), 256>>>(x);
    split_w_kernel<<<dim3(OUT_DIM / 32, IN_DIM / 32), dim3(32, 8)>>>(cw);

    static int attr_done = 0;
    if (!attr_done) {
        cudaFuncSetAttribute(gemm_bf16x3_kernel,
                             cudaFuncAttributeMaxDynamicSharedMemorySize,
                             SMEM_TOTAL);
        attr_done = 1;
    }
    dim3 grid(OUT_DIM / BN, BATCH / BM);   // (32, 64)
    gemm_bf16x3_kernel<<<grid, 256, SMEM_TOTAL>>>(out);
}